// round 2
// baseline (speedup 1.0000x reference)
#include <cuda_runtime.h>
#include <cstdint>

// Problem constants
#define SN 96        // slices (ROW)
#define NB 32        // batch B
#define MM 3072      // SN*NB recurrent rows
#define OLEN 48      // COL (original slice len)
#define SLT 143      // SN + OLEN - 1 time steps
#define HH 128       // hidden
#define DD 32        // input feature dim
#define KK 288       // fused GEMM K = 2H + D
#define NG 768       // gate width = 6H

typedef unsigned long long ull;

// ---------------- device scratch (no allocations allowed) ----------------
__device__ float g_W[KK * NG];      // fused, column-permuted weight [288][768]
__device__ float g_bias[NG];        // fused, permuted bias
__device__ float g_hrow[2][MM * HH];
__device__ float g_hcol[2][MM * HH];

// ---------------- helpers ----------------
__device__ __forceinline__ ull pack2(float x, float y) {
    ull r;
    asm("mov.b64 %0, {%1, %2};" : "=l"(r) : "f"(x), "f"(y));
    return r;
}
__device__ __forceinline__ void unpack2(ull v, float& x, float& y) {
    asm("mov.b64 {%0, %1}, %2;" : "=f"(x), "=f"(y) : "l"(v));
}
__device__ __forceinline__ void fma2(ull& acc, ull a, ull b) {
    asm("fma.rn.f32x2 %0, %1, %2, %0;" : "+l"(acc) : "l"(a), "l"(b));
}
__device__ __forceinline__ float sigmoid_f(float x) {
    return 1.0f / (1.0f + __expf(-x));
}
__device__ __forceinline__ float tanh_f(float x) {
    float ax = fabsf(x);
    float e  = __expf(-2.0f * ax);
    float r  = (1.0f - e) / (1.0f + e);
    return copysignf(r, x);
}

// ---------------- init: zero states ----------------
__global__ void zero_states_kernel() {
    int n = 2 * MM * HH;
    for (int i = blockIdx.x * blockDim.x + threadIdx.x; i < n; i += gridDim.x * blockDim.x) {
        g_hrow[0][i % (MM * HH)] = 0.f;  // covered twice over halves below; simpler explicit:
        ;
    }
}
// simpler correct version (used instead):
__global__ void zero_all_kernel() {
    int n = MM * HH;
    for (int i = blockIdx.x * blockDim.x + threadIdx.x; i < n; i += gridDim.x * blockDim.x) {
        g_hrow[0][i] = 0.f; g_hrow[1][i] = 0.f;
        g_hcol[0][i] = 0.f; g_hcol[1][i] = 0.f;
    }
}

// ---------------- prep: fused + permuted weights ----------------
// gate feature layout (K): [0:128)=h_row, [128:256)=h_col, [256:288)=x
// gate output permutation: p = u*6 + g, with original gate column oc = g*128 + u
//   g: 0=u_r 1=o_r 2=u_c 3=o_c 4=i_r 5=i_c
__global__ void prep_weights_kernel(
    const float* __restrict__ Wf,  const float* __restrict__ bf,
    const float* __restrict__ Wrm, const float* __restrict__ brm,
    const float* __restrict__ Wcm, const float* __restrict__ bcm,
    const float* __restrict__ Wrxm, const float* __restrict__ brxm,
    const float* __restrict__ Wcxm, const float* __restrict__ bcxm)
{
    int p = blockIdx.x;              // 0..767
    int u = p / 6, g = p % 6;
    int oc = g * 128 + u;            // original gate column

    __shared__ float sWf[KK];
    for (int i = threadIdx.x; i < KK; i += blockDim.x) sWf[i] = Wf[oc * KK + i];
    __syncthreads();

    int k = threadIdx.x;             // 288 threads
    if (k < KK) {
        float acc = 0.f;
        if (k < HH) {
            #pragma unroll 4
            for (int h = 0; h < HH; h++) acc += Wrm[h * HH + k] * sWf[h];
        } else if (k < 2 * HH) {
            int kk = k - HH;
            #pragma unroll 4
            for (int h = 0; h < HH; h++) acc += Wcm[h * HH + kk] * sWf[HH + h];
        } else {
            int d = k - 2 * HH;
            #pragma unroll 4
            for (int h = 0; h < HH; h++)
                acc += Wrxm[h * DD + d] * sWf[h] + Wcxm[h * DD + d] * sWf[HH + h];
            acc += sWf[2 * HH + d];
        }
        g_W[k * NG + p] = acc;
    }
    if (threadIdx.x == 0) {
        float bacc = bf[oc];
        for (int h = 0; h < HH; h++)
            bacc += (brxm[h] + brm[h]) * sWf[h] + (bcxm[h] + bcm[h]) * sWf[HH + h];
        g_bias[p] = bacc;
    }
}

// ---------------- per-step fused GEMM + gating ----------------
// grid: (4 n-tiles of 192, 48 m-tiles of 64), 256 threads
// thread tile: 4 rows x 12 cols (= 2 full gate units)
__global__ __launch_bounds__(256) void step_kernel(
    const float* __restrict__ input,   // [B, SN, OLEN, D]
    float* __restrict__ out,
    int t, int pin, int write_hidden)
{
    __shared__ float sF[64][36];   // feat tile [row][k-chunk], padded
    __shared__ float sW[32][192];  // weight tile [k-chunk][cols]

    const float* __restrict__ hrow_in = g_hrow[pin];
    const float* __restrict__ hcol_in = g_hcol[pin];
    float* __restrict__ hrow_out = g_hrow[pin ^ 1];
    float* __restrict__ hcol_out = g_hcol[pin ^ 1];

    const int tid   = threadIdx.x;
    const int colt  = tid & 15;    // 0..15
    const int rowt  = tid >> 4;    // 0..15
    const int mBase = blockIdx.y * 64;
    const int nBase = blockIdx.x * 192;

    ull acc[4][6];
    #pragma unroll
    for (int i = 0; i < 4; i++)
        #pragma unroll
        for (int j = 0; j < 6; j++) acc[i][j] = 0ull;

    const int lk  = tid & 31;      // k within chunk
    const int lm0 = tid >> 5;      // 0..7

    for (int kc = 0; kc < 9; ++kc) {
        // --- load feature tile (64 rows x 32 k) ---
        int kg = kc * 32 + lk;
        #pragma unroll
        for (int mmi = 0; mmi < 8; ++mmi) {
            int ml = lm0 + mmi * 8;
            int m  = mBase + ml;
            float v;
            if (kc < 4) {
                v = hrow_in[m * HH + kg];
            } else if (kc < 8) {
                v = hcol_in[m * HH + (kg - HH)];
            } else {
                int r = m >> 5, b = m & 31;
                int c = t - r;
                v = (c >= 0 && c < OLEN)
                    ? input[(((b * SN) + r) * OLEN + c) * DD + (kg - 2 * HH)]
                    : 0.f;
            }
            sF[ml][lk] = v;
        }
        // --- load weight tile (32 k x 192 cols) as float4 ---
        #pragma unroll
        for (int it = 0; it < 6; ++it) {
            int lin = tid + it * 256;     // 0..1535
            int k   = lin / 48;
            int j4  = lin % 48;
            float4 w = *reinterpret_cast<const float4*>(&g_W[(kc * 32 + k) * NG + nBase + j4 * 4]);
            *reinterpret_cast<float4*>(&sW[k][j4 * 4]) = w;
        }
        __syncthreads();

        #pragma unroll 4
        for (int k = 0; k < 32; ++k) {
            ull f[4];
            #pragma unroll
            for (int i = 0; i < 4; i++) {
                float fv = sF[rowt * 4 + i][k];
                f[i] = pack2(fv, fv);
            }
            const ull* wp = reinterpret_cast<const ull*>(&sW[k][colt * 12]);
            ull w[6];
            #pragma unroll
            for (int j = 0; j < 6; j++) w[j] = wp[j];
            #pragma unroll
            for (int i = 0; i < 4; i++)
                #pragma unroll
                for (int j = 0; j < 6; j++) fma2(acc[i][j], f[i], w[j]);
        }
        __syncthreads();
    }

    // --- epilogue: bias + gating + state update + outputs ---
    float bloc[12];
    #pragma unroll
    for (int j = 0; j < 12; j++) bloc[j] = g_bias[nBase + colt * 12 + j];

    const long long HR_BASE = (long long)MM * SLT * 256;                 // 112,459,776
    const long long HC_BASE = HR_BASE + (long long)NB * SN * HH;         // + 393,216

    #pragma unroll
    for (int i = 0; i < 4; i++) {
        int m = mBase + rowt * 4 + i;
        int r = m >> 5, b = m & 31;
        float gv[12];
        #pragma unroll
        for (int j = 0; j < 6; j++) {
            float x, y;
            unpack2(acc[i][j], x, y);
            gv[2 * j]     = x + bloc[2 * j];
            gv[2 * j + 1] = y + bloc[2 * j + 1];
        }
        #pragma unroll
        for (int uu = 0; uu < 2; ++uu) {
            float a_ur = gv[uu * 6 + 0];
            float a_or = gv[uu * 6 + 1];
            float a_uc = gv[uu * 6 + 2];
            float a_oc = gv[uu * 6 + 3];
            float a_ir = gv[uu * 6 + 4];
            float a_ic = gv[uu * 6 + 5];
            int U = (nBase / 6) + colt * 2 + uu;   // global hidden unit 0..127

            float hr = hrow_in[m * HH + U];
            float hc = hcol_in[m * HH + U];

            float ur = sigmoid_f(a_ur);
            float og = sigmoid_f(a_or);
            float uc = sigmoid_f(a_uc);
            float oc = sigmoid_f(a_oc);
            float ir = tanh_f(a_ir);
            float ic = tanh_f(a_ic);

            float hrn = tanh_f((1.f - ur) * hr + ur * ir) * og;
            float hcn = tanh_f((1.f - uc) * hc + uc * ic) * oc;

            long long ob = ((long long)m * SLT + t) * 256;
            out[ob + U]       = hrn;
            out[ob + 128 + U] = hcn;

            hrow_out[m * HH + U] = hrn;
            int ms = m + NB; if (ms >= MM) ms -= MM;   // roll(h_col, B)
            hcol_out[ms * HH + U] = hcn;

            if (write_hidden) {
                if (t - r == OLEN - 1)   // last active step of slice r
                    out[HR_BASE + ((long long)b * SN + r) * HH + U] = hrn;
                if (r == SN - 1 && t >= SN - 1)  // slice 95 col states (pre-roll)
                    out[HC_BASE + ((long long)b * OLEN + (t - (SN - 1))) * HH + U] = hcn;
            }
        }
    }
}

// ---------------- launch ----------------
extern "C" void kernel_launch(void* const* d_in, const int* in_sizes, int n_in,
                              void* d_out, int out_size) {
    const float* input = (const float*)d_in[0];
    const float* Wf    = (const float*)d_in[1];
    const float* bf    = (const float*)d_in[2];
    const float* Wrm   = (const float*)d_in[3];
    const float* brm   = (const float*)d_in[4];
    const float* Wcm   = (const float*)d_in[5];
    const float* bcm   = (const float*)d_in[6];
    const float* Wrxm  = (const float*)d_in[7];
    const float* brxm  = (const float*)d_in[8];
    const float* Wcxm  = (const float*)d_in[9];
    const float* bcxm  = (const float*)d_in[10];
    float* out = (float*)d_out;

    long long need = (long long)MM * SLT * 256 + (long long)NB * SN * HH + (long long)NB * OLEN * HH;
    int write_hidden = ((long long)out_size >= need) ? 1 : 0;

    zero_all_kernel<<<256, 256>>>();
    prep_weights_kernel<<<NG, KK>>>(Wf, bf, Wrm, brm, Wcm, bcm, Wrxm, brxm, Wcxm, bcxm);

    dim3 grid(4, 48);
    for (int t = 0; t < SLT; ++t) {
        step_kernel<<<grid, 256>>>(input, out, t, t & 1, write_hidden);
    }
}

// round 3
// speedup vs baseline: 1.4152x; 1.4152x over previous
#include <cuda_runtime.h>
#include <cstdint>

// Problem constants
#define SN 96        // slices (ROW)
#define NB 32        // batch B
#define MM 3072      // SN*NB recurrent rows
#define OLEN 48      // COL (original slice len)
#define SLT 143      // SN + OLEN - 1 time steps
#define HH 128       // hidden
#define DD 32        // input feature dim
#define KK 288       // fused GEMM K = 2H + D
#define NG 768       // gate width = 6H

typedef unsigned long long ull;

// ---------------- device scratch (no allocations allowed) ----------------
__device__ float g_W[KK * NG];      // fused, column-permuted weight [288][768]
__device__ float g_bias[NG];        // fused, permuted bias
__device__ float g_hrow[2][MM * HH];
__device__ float g_hcol[2][MM * HH];

// ---------------- helpers ----------------
__device__ __forceinline__ ull pack2(float x, float y) {
    ull r;
    asm("mov.b64 %0, {%1, %2};" : "=l"(r) : "f"(x), "f"(y));
    return r;
}
__device__ __forceinline__ void unpack2(ull v, float& x, float& y) {
    asm("mov.b64 {%0, %1}, %2;" : "=f"(x), "=f"(y) : "l"(v));
}
__device__ __forceinline__ void fma2(ull& acc, ull a, ull b) {
    asm("fma.rn.f32x2 %0, %1, %2, %0;" : "+l"(acc) : "l"(a), "l"(b));
}
__device__ __forceinline__ float tanh_ap(float x) {
    float y;
    asm("tanh.approx.f32 %0, %1;" : "=f"(y) : "f"(x));
    return y;
}
__device__ __forceinline__ float sigmoid_f(float x) {
    // sigmoid(x) = 0.5*tanh(0.5x) + 0.5
    return fmaf(0.5f, tanh_ap(0.5f * x), 0.5f);
}

// ---------------- init: zero states ----------------
__global__ void zero_all_kernel() {
    int n = MM * HH;
    for (int i = blockIdx.x * blockDim.x + threadIdx.x; i < n; i += gridDim.x * blockDim.x) {
        g_hrow[0][i] = 0.f; g_hrow[1][i] = 0.f;
        g_hcol[0][i] = 0.f; g_hcol[1][i] = 0.f;
    }
}

// ---------------- prep: fused + permuted weights ----------------
// gate feature layout (K): [0:128)=h_row, [128:256)=h_col, [256:288)=x
// gate output permutation: p = u*6 + g, original gate column oc = g*128 + u
//   g: 0=u_r 1=o_r 2=u_c 3=o_c 4=i_r 5=i_c
__global__ void prep_weights_kernel(
    const float* __restrict__ Wf,  const float* __restrict__ bf,
    const float* __restrict__ Wrm, const float* __restrict__ brm,
    const float* __restrict__ Wcm, const float* __restrict__ bcm,
    const float* __restrict__ Wrxm, const float* __restrict__ brxm,
    const float* __restrict__ Wcxm, const float* __restrict__ bcxm)
{
    int p = blockIdx.x;              // 0..767
    int u = p / 6, g = p % 6;
    int oc = g * 128 + u;            // original gate column

    __shared__ float sWf[KK];
    for (int i = threadIdx.x; i < KK; i += blockDim.x) sWf[i] = Wf[oc * KK + i];
    __syncthreads();

    int k = threadIdx.x;             // 288 threads
    if (k < KK) {
        float acc = 0.f;
        if (k < HH) {
            #pragma unroll 4
            for (int h = 0; h < HH; h++) acc += Wrm[h * HH + k] * sWf[h];
        } else if (k < 2 * HH) {
            int kk = k - HH;
            #pragma unroll 4
            for (int h = 0; h < HH; h++) acc += Wcm[h * HH + kk] * sWf[HH + h];
        } else {
            int d = k - 2 * HH;
            #pragma unroll 4
            for (int h = 0; h < HH; h++)
                acc += Wrxm[h * DD + d] * sWf[h] + Wcxm[h * DD + d] * sWf[HH + h];
            acc += sWf[2 * HH + d];
        }
        g_W[k * NG + p] = acc;
    }
    if (threadIdx.x == 0) {
        float bacc = bf[oc];
        for (int h = 0; h < HH; h++)
            bacc += (brxm[h] + brm[h]) * sWf[h] + (bcxm[h] + bcm[h]) * sWf[HH + h];
        g_bias[p] = bacc;
    }
}

// ---------------- per-step fused GEMM + gating ----------------
// grid: (8 n-tiles of 96, 48 m-tiles of 64), 256 threads.
// warp grid 4(row)x2(col), warp tile 16x48; lane grid 4x8, thread tile 4 rows x 6 cols
// (= exactly 1 hidden unit's 6 permuted gates per thread column group).
__global__ __launch_bounds__(256, 3) void step_kernel(
    const float* __restrict__ input,   // [B, SN, OLEN, D]
    float* __restrict__ out,
    int t, int pin, int write_hidden)
{
    __shared__ float sF[64][33];   // feature tile [row][k], padded
    __shared__ float sW[32][96];   // weight tile [k][col]

    const float* __restrict__ hrow_in = g_hrow[pin];
    const float* __restrict__ hcol_in = g_hcol[pin];
    float* __restrict__ hrow_out = g_hrow[pin ^ 1];
    float* __restrict__ hcol_out = g_hcol[pin ^ 1];

    const int tid    = threadIdx.x;
    const int lane   = tid & 31;
    const int warp   = tid >> 5;
    const int warp_r = warp & 3;       // 0..3
    const int warp_c = warp >> 2;      // 0..1
    const int laneR  = lane >> 3;      // 0..3
    const int laneC  = lane & 7;       // 0..7
    const int mBase  = blockIdx.y * 64;
    const int nBase  = blockIdx.x * 96;

    // both slices of this block strictly pre-start -> all 64 rows share one state
    const bool dup = ((mBase >> 5) > t);

    const int myRow = warp_r * 16 + laneR * 4;     // local row of thread's first row
    const int myCol = warp_c * 48 + laneC * 6;     // local col of thread's 6 gate cols

    ull acc[4][3];
    #pragma unroll
    for (int i = 0; i < 4; i++)
        #pragma unroll
        for (int j = 0; j < 3; j++) acc[i][j] = 0ull;

    const int lk  = tid & 31;      // k within chunk
    const int lm0 = tid >> 5;      // 0..7

    for (int kc = 0; kc < 9; ++kc) {
        // --- load feature tile (64 rows x 32 k) ---
        int kg = kc * 32 + lk;
        #pragma unroll
        for (int mmi = 0; mmi < 8; ++mmi) {
            int ml = lm0 + mmi * 8;
            int m  = mBase + ml;
            float v;
            if (kc < 4) {
                v = hrow_in[m * HH + kg];
            } else if (kc < 8) {
                v = hcol_in[m * HH + (kg - HH)];
            } else {
                int r = m >> 5, b = m & 31;
                int c = t - r;
                v = (c >= 0 && c < OLEN)
                    ? input[(((b * SN) + r) * OLEN + c) * DD + (kg - 2 * HH)]
                    : 0.f;
            }
            sF[ml][lk] = v;
        }
        // --- load weight tile (32 k x 96 cols) as float4 ---
        #pragma unroll
        for (int it = 0; it < 3; ++it) {
            int lin = tid + it * 256;     // 0..767 float4 slots
            int k   = lin / 24;
            int j4  = lin % 24;
            float4 w = *reinterpret_cast<const float4*>(&g_W[(kc * 32 + k) * NG + nBase + j4 * 4]);
            *reinterpret_cast<float4*>(&sW[k][j4 * 4]) = w;
        }
        __syncthreads();

        if (!dup) {
            #pragma unroll 8
            for (int k = 0; k < 32; ++k) {
                const ull* wp = reinterpret_cast<const ull*>(&sW[k][myCol]);
                ull w0 = wp[0], w1 = wp[1], w2 = wp[2];
                #pragma unroll
                for (int i = 0; i < 4; i++) {
                    float fv = sF[myRow + i][k];
                    ull f = pack2(fv, fv);
                    fma2(acc[i][0], f, w0);
                    fma2(acc[i][1], f, w1);
                    fma2(acc[i][2], f, w2);
                }
            }
        } else {
            // all rows identical: compute one row only
            #pragma unroll 8
            for (int k = 0; k < 32; ++k) {
                const ull* wp = reinterpret_cast<const ull*>(&sW[k][myCol]);
                ull w0 = wp[0], w1 = wp[1], w2 = wp[2];
                float fv = sF[myRow][k];
                ull f = pack2(fv, fv);
                fma2(acc[0][0], f, w0);
                fma2(acc[0][1], f, w1);
                fma2(acc[0][2], f, w2);
            }
        }
        __syncthreads();
    }

    // --- epilogue: bias + gating + state update + outputs ---
    float bloc[6];
    #pragma unroll
    for (int j = 0; j < 6; j++) bloc[j] = g_bias[nBase + myCol + j];

    const int U = blockIdx.x * 16 + warp_c * 8 + laneC;   // global hidden unit

    const long long HR_BASE = (long long)MM * SLT * 256;
    const long long HC_BASE = HR_BASE + (long long)NB * SN * HH;

    const int nrows = dup ? 1 : 4;

    #pragma unroll 4
    for (int i = 0; i < nrows; i++) {
        int m = mBase + myRow + i;
        int r = m >> 5, b = m & 31;

        float a_ur, a_or, a_uc, a_oc, a_ir, a_ic;
        unpack2(acc[i][0], a_ur, a_or);
        unpack2(acc[i][1], a_uc, a_oc);
        unpack2(acc[i][2], a_ir, a_ic);
        a_ur += bloc[0]; a_or += bloc[1];
        a_uc += bloc[2]; a_oc += bloc[3];
        a_ir += bloc[4]; a_ic += bloc[5];

        float hr = hrow_in[m * HH + U];
        float hc = hcol_in[m * HH + U];

        float ur = sigmoid_f(a_ur);
        float og = sigmoid_f(a_or);
        float uc = sigmoid_f(a_uc);
        float oc = sigmoid_f(a_oc);
        float ir = tanh_ap(a_ir);
        float ic = tanh_ap(a_ic);

        float hrn = tanh_ap((1.f - ur) * hr + ur * ir) * og;
        float hcn = tanh_ap((1.f - uc) * hc + uc * ic) * oc;

        if (!dup) {
            long long ob = ((long long)m * SLT + t) * 256;
            out[ob + U]       = hrn;
            out[ob + 128 + U] = hcn;
            hrow_out[m * HH + U] = hrn;
            int ms = m + NB; if (ms >= MM) ms -= MM;   // roll(h_col, B)
            hcol_out[ms * HH + U] = hcn;

            if (write_hidden) {
                if (t - r == OLEN - 1)
                    out[HR_BASE + ((long long)b * SN + r) * HH + U] = hrn;
                if (r == SN - 1 && t >= SN - 1)
                    out[HC_BASE + ((long long)b * OLEN + (t - (SN - 1))) * HH + U] = hcn;
            }
        } else {
            // replicate identical result to all 4 rows of this thread
            #pragma unroll
            for (int ii = 0; ii < 4; ii++) {
                int mr = mBase + myRow + ii;
                long long ob = ((long long)mr * SLT + t) * 256;
                out[ob + U]       = hrn;
                out[ob + 128 + U] = hcn;
                hrow_out[mr * HH + U] = hrn;
                int ms = mr + NB; if (ms >= MM) ms -= MM;
                hcol_out[ms * HH + U] = hcn;
            }
            // hidden picks never fire for pre-start rows
        }
    }
}

// ---------------- launch ----------------
extern "C" void kernel_launch(void* const* d_in, const int* in_sizes, int n_in,
                              void* d_out, int out_size) {
    const float* input = (const float*)d_in[0];
    const float* Wf    = (const float*)d_in[1];
    const float* bf    = (const float*)d_in[2];
    const float* Wrm   = (const float*)d_in[3];
    const float* brm   = (const float*)d_in[4];
    const float* Wcm   = (const float*)d_in[5];
    const float* bcm   = (const float*)d_in[6];
    const float* Wrxm  = (const float*)d_in[7];
    const float* brxm  = (const float*)d_in[8];
    const float* Wcxm  = (const float*)d_in[9];
    const float* bcxm  = (const float*)d_in[10];
    float* out = (float*)d_out;

    long long need = (long long)MM * SLT * 256 + (long long)NB * SN * HH + (long long)NB * OLEN * HH;
    int write_hidden = ((long long)out_size >= need) ? 1 : 0;

    zero_all_kernel<<<256, 256>>>();
    prep_weights_kernel<<<NG, KK>>>(Wf, bf, Wrm, brm, Wcm, bcm, Wrxm, brxm, Wcxm, bcxm);

    dim3 grid(8, 48);
    for (int t = 0; t < SLT; ++t) {
        step_kernel<<<grid, 256>>>(input, out, t, t & 1, write_hidden);
    }
}